// round 2
// baseline (speedup 1.0000x reference)
#include <cuda_runtime.h>
#include <math.h>

#define NSEG 50000
#define MROWS 800000
#define DDIM 128
#define KDIM 256   // 2*DDIM
#define ODIM 128

// Scratch (no allocations allowed in kernel_launch)
__device__ int   g_starts[NSEG + 1];
__device__ float g_pooled[(long long)NSEG * KDIM];

// ---------------------------------------------------------------------------
// Kernel 1: segment boundary detection, 4 ids per thread.
// ids sorted, every id in [0,NSEG) present. Dtype probe: word [MROWS-1] is the
// high half of an int64 element (0 since ids < 2^31) iff the array is int64;
// for int32 it equals NSEG-1 != 0.
// ---------------------------------------------------------------------------
__global__ void boundary_kernel(const void* __restrict__ segraw) {
    int t = blockIdx.x * blockDim.x + threadIdx.x;
    int base = t * 4;
    if (base >= MROWS) return;
    const int* s32 = (const int*)segraw;
    bool is64 = (s32[MROWS - 1] == 0);
    int v[5];
    if (is64) {
        const long long* s = (const long long*)segraw;
        v[0] = (base > 0) ? (int)s[base - 1] : -1;
        longlong2 a = *(const longlong2*)&s[base];
        longlong2 b = *(const longlong2*)&s[base + 2];
        v[1] = (int)a.x; v[2] = (int)a.y; v[3] = (int)b.x; v[4] = (int)b.y;
    } else {
        v[0] = (base > 0) ? s32[base - 1] : -1;
        int4 a = *(const int4*)&s32[base];
        v[1] = a.x; v[2] = a.y; v[3] = a.z; v[4] = a.w;
    }
#pragma unroll
    for (int j = 0; j < 4; ++j)
        if (v[j + 1] != v[j]) g_starts[v[j + 1]] = base + j;
    if (base == 0) g_starts[NSEG] = MROWS;
}

// ---------------------------------------------------------------------------
// Kernel 2: segmented max+mean pooling. One warp per segment, lane owns one
// float4 of the 128-dim row (full 512B coalesced row per step). Unrolled x4
// with independent accumulator sets for MLP=4.
// ---------------------------------------------------------------------------
__global__ __launch_bounds__(256) void pool_kernel(const float* __restrict__ lane) {
    int warp = threadIdx.x >> 5;
    int lid  = threadIdx.x & 31;
    int n = blockIdx.x * 8 + warp;
    if (n >= NSEG) return;
    int start = g_starts[n];
    int len   = g_starts[n + 1] - start;

    const float4* p = reinterpret_cast<const float4*>(lane) + (long long)start * 32 + lid;

    float4 m0 = make_float4(-INFINITY, -INFINITY, -INFINITY, -INFINITY);
    float4 m1 = m0, m2 = m0, m3 = m0;
    float4 s0 = make_float4(0.f, 0.f, 0.f, 0.f);
    float4 s1 = s0, s2 = s0, s3 = s0;

    int r = 0;
    for (; r + 4 <= len; r += 4) {
        float4 v0 = p[0], v1 = p[32], v2 = p[64], v3 = p[96];
        p += 128;
        m0.x = fmaxf(m0.x, v0.x); s0.x += v0.x; m0.y = fmaxf(m0.y, v0.y); s0.y += v0.y;
        m0.z = fmaxf(m0.z, v0.z); s0.z += v0.z; m0.w = fmaxf(m0.w, v0.w); s0.w += v0.w;
        m1.x = fmaxf(m1.x, v1.x); s1.x += v1.x; m1.y = fmaxf(m1.y, v1.y); s1.y += v1.y;
        m1.z = fmaxf(m1.z, v1.z); s1.z += v1.z; m1.w = fmaxf(m1.w, v1.w); s1.w += v1.w;
        m2.x = fmaxf(m2.x, v2.x); s2.x += v2.x; m2.y = fmaxf(m2.y, v2.y); s2.y += v2.y;
        m2.z = fmaxf(m2.z, v2.z); s2.z += v2.z; m2.w = fmaxf(m2.w, v2.w); s2.w += v2.w;
        m3.x = fmaxf(m3.x, v3.x); s3.x += v3.x; m3.y = fmaxf(m3.y, v3.y); s3.y += v3.y;
        m3.z = fmaxf(m3.z, v3.z); s3.z += v3.z; m3.w = fmaxf(m3.w, v3.w); s3.w += v3.w;
    }
    for (; r < len; ++r) {
        float4 v = p[0];
        p += 32;
        m0.x = fmaxf(m0.x, v.x); s0.x += v.x; m0.y = fmaxf(m0.y, v.y); s0.y += v.y;
        m0.z = fmaxf(m0.z, v.z); s0.z += v.z; m0.w = fmaxf(m0.w, v.w); s0.w += v.w;
    }
    float4 mx, sm;
    mx.x = fmaxf(fmaxf(m0.x, m1.x), fmaxf(m2.x, m3.x));
    mx.y = fmaxf(fmaxf(m0.y, m1.y), fmaxf(m2.y, m3.y));
    mx.z = fmaxf(fmaxf(m0.z, m1.z), fmaxf(m2.z, m3.z));
    mx.w = fmaxf(fmaxf(m0.w, m1.w), fmaxf(m2.w, m3.w));
    sm.x = (s0.x + s1.x) + (s2.x + s3.x);
    sm.y = (s0.y + s1.y) + (s2.y + s3.y);
    sm.z = (s0.z + s1.z) + (s2.z + s3.z);
    sm.w = (s0.w + s1.w) + (s2.w + s3.w);

    float inv = 1.0f / (float)len;
    float4* o = reinterpret_cast<float4*>(g_pooled + (long long)n * KDIM);
    o[lid] = mx;
    o[32 + lid] = make_float4(sm.x * inv, sm.y * inv, sm.z * inv, sm.w * inv);
}

// ---------------------------------------------------------------------------
// Kernel 3: out = relu(pooled @ W^T + b). f32x2 FMA packed ALONG K:
// acc2[m][n] += (a_k, a_{k+1}) * (b_k, b_{k+1}); horizontal add at epilogue.
// Both operands are natural 16B shared loads (ulonglong2) -> zero pack movs.
// Smem tiles stored K-contiguous with XOR swizzle on the float4 column to
// avoid bank conflicts between the two ty-groups of a warp.
// ---------------------------------------------------------------------------
#define BM 128
#define BN 64
#define BK 32
#define TM 8
#define TN 4

__device__ __forceinline__ void ffma2(unsigned long long& d,
                                      unsigned long long a,
                                      unsigned long long b) {
    asm("fma.rn.f32x2 %0, %1, %2, %0;" : "+l"(d) : "l"(a), "l"(b));
}
__device__ __forceinline__ void unpack2(unsigned long long v, float& x, float& y) {
    asm("mov.b64 {%0, %1}, %2;" : "=f"(x), "=f"(y) : "l"(v));
}

__global__ __launch_bounds__(256) void gemm_kernel(const float* __restrict__ W,
                                                   const float* __restrict__ bias,
                                                   float* __restrict__ out) {
    __shared__ float As[BM][BK];   // k-contiguous, float4-column swizzled
    __shared__ float Bs[BN][BK];

    const int tid = threadIdx.x;
    const int tx = tid & 15;   // col group: cols tx*4 .. tx*4+3
    const int ty = tid >> 4;   // row group: rows ty*8 .. ty*8+7
    const int bm = blockIdx.x * BM;
    const int bn = blockIdx.y * BN;

    unsigned long long acc[TM][TN];
#pragma unroll
    for (int i = 0; i < TM; ++i)
#pragma unroll
        for (int j = 0; j < TN; ++j) acc[i][j] = 0ull;

    for (int kt = 0; kt < KDIM; kt += BK) {
        // A tile: 128 rows x 32 floats = 1024 float4, 4 per thread. Direct
        // (non-transposed) copy; swizzle float4 column by (row>>3)&7.
#pragma unroll
        for (int i = 0; i < 4; ++i) {
            int idx = tid + i * 256;
            int row = idx >> 3;
            int c4  = idx & 7;
            float4 v = make_float4(0.f, 0.f, 0.f, 0.f);
            int grow = bm + row;
            if (grow < NSEG)
                v = *(const float4*)&g_pooled[(long long)grow * KDIM + kt + c4 * 4];
            int sc = c4 ^ ((row >> 3) & 7);
            *(float4*)&As[row][sc * 4] = v;
        }
        // B tile: 64 rows x 32 floats = 512 float4, 2 per thread.
#pragma unroll
        for (int i = 0; i < 2; ++i) {
            int idx = tid + i * 256;
            int row = idx >> 3;
            int c4  = idx & 7;
            float4 v = *(const float4*)&W[(long long)(bn + row) * KDIM + kt + c4 * 4];
            int sc = c4 ^ ((row >> 2) & 7);
            *(float4*)&Bs[row][sc * 4] = v;
        }
        __syncthreads();

#pragma unroll
        for (int k4 = 0; k4 < BK / 4; ++k4) {
            ulonglong2 a[TM];
            int asc = (k4 ^ (ty & 7)) * 4;
#pragma unroll
            for (int i = 0; i < TM; ++i)
                a[i] = *(const ulonglong2*)&As[ty * TM + i][asc];
            ulonglong2 b[TN];
            int bsc = (k4 ^ (tx & 7)) * 4;
#pragma unroll
            for (int j = 0; j < TN; ++j)
                b[j] = *(const ulonglong2*)&Bs[tx * TN + j][bsc];
#pragma unroll
            for (int i = 0; i < TM; ++i)
#pragma unroll
                for (int j = 0; j < TN; ++j) {
                    ffma2(acc[i][j], a[i].x, b[j].x);
                    ffma2(acc[i][j], a[i].y, b[j].y);
                }
        }
        __syncthreads();
    }

    // Epilogue: horizontal add of the two K-lanes, bias + relu, float4 store.
    const int col = bn + tx * TN;
    float4 bv = *(const float4*)&bias[col];
#pragma unroll
    for (int i = 0; i < TM; ++i) {
        int row = bm + ty * TM + i;
        if (row < NSEG) {
            float lo, hi;
            float4 r;
            unpack2(acc[i][0], lo, hi); r.x = fmaxf(lo + hi + bv.x, 0.f);
            unpack2(acc[i][1], lo, hi); r.y = fmaxf(lo + hi + bv.y, 0.f);
            unpack2(acc[i][2], lo, hi); r.z = fmaxf(lo + hi + bv.z, 0.f);
            unpack2(acc[i][3], lo, hi); r.w = fmaxf(lo + hi + bv.w, 0.f);
            *(float4*)&out[(long long)row * ODIM + col] = r;
        }
    }
}

// ---------------------------------------------------------------------------
// Inputs (metadata order): obs_encoding (unused), lane_encoding, same_obs_mask,
// W, b. Output: float32 [NSEG, ODIM].
// ---------------------------------------------------------------------------
extern "C" void kernel_launch(void* const* d_in, const int* in_sizes, int n_in,
                              void* d_out, int out_size) {
    const float* lane = (const float*)d_in[1];
    const void*  seg  = d_in[2];
    const float* W    = (const float*)d_in[3];
    const float* bias = (const float*)d_in[4];
    float* out = (float*)d_out;

    boundary_kernel<<<(MROWS / 4 + 255) / 256, 256>>>(seg);
    pool_kernel<<<(NSEG + 7) / 8, 256>>>(lane);
    dim3 grid((NSEG + BM - 1) / BM, ODIM / BN);
    gemm_kernel<<<grid, 256>>>(W, bias, out);
}

// round 4
// speedup vs baseline: 1.6440x; 1.6440x over previous
#include <cuda_runtime.h>
#include <math.h>
#include <stdint.h>

#define NSEG 50000
#define NSEG_PAD 50048
#define MROWS 800000
#define KDIM 256   // 2*D
#define ODIM 128

// Scratch (device globals zero-initialized -> padded rows of g_pooled are 0)
__device__ int   g_starts[NSEG + 1];
__device__ float g_pooled[(long long)NSEG_PAD * KDIM];

// Round-to-nearest tf32 (plain PTX, supported on compute_103 family target)
__device__ __forceinline__ float to_tf32(float x) {
    float r; asm("cvt.rna.tf32.f32 %0, %1;" : "=f"(r) : "f"(x)); return r;
}

// ---------------------------------------------------------------------------
// Kernel 1: segment boundary detection, 4 ids per thread (dtype probe for
// int64 vs int32: word [MROWS-1] is 0 iff ids are little-endian int64).
// ---------------------------------------------------------------------------
__global__ void boundary_kernel(const void* __restrict__ segraw) {
    int t = blockIdx.x * blockDim.x + threadIdx.x;
    int base = t * 4;
    if (base >= MROWS) return;
    const int* s32 = (const int*)segraw;
    bool is64 = (s32[MROWS - 1] == 0);
    int v[5];
    if (is64) {
        const long long* s = (const long long*)segraw;
        v[0] = (base > 0) ? (int)s[base - 1] : -1;
        longlong2 a = *(const longlong2*)&s[base];
        longlong2 b = *(const longlong2*)&s[base + 2];
        v[1] = (int)a.x; v[2] = (int)a.y; v[3] = (int)b.x; v[4] = (int)b.y;
    } else {
        v[0] = (base > 0) ? s32[base - 1] : -1;
        int4 a = *(const int4*)&s32[base];
        v[1] = a.x; v[2] = a.y; v[3] = a.z; v[4] = a.w;
    }
#pragma unroll
    for (int j = 0; j < 4; ++j)
        if (v[j + 1] != v[j]) g_starts[v[j + 1]] = base + j;
    if (base == 0) g_starts[NSEG] = MROWS;
}

// ---------------------------------------------------------------------------
// Kernel 2: segmented max+mean pooling (R1 known-good version).
// One warp per segment, lane owns a float4 of the 128-dim row.
// ---------------------------------------------------------------------------
__global__ void pool_kernel(const float* __restrict__ lane) {
    int warp = threadIdx.x >> 5;
    int lid  = threadIdx.x & 31;
    int n = blockIdx.x * 4 + warp;
    if (n >= NSEG) return;
    int start = g_starts[n];
    int end   = g_starts[n + 1];

    const float4* p = reinterpret_cast<const float4*>(lane) + (long long)start * 32 + lid;
    float4 mx = make_float4(-INFINITY, -INFINITY, -INFINITY, -INFINITY);
    float4 sm = make_float4(0.f, 0.f, 0.f, 0.f);

    for (int r = start; r < end; ++r, p += 32) {
        float4 v = *p;
        mx.x = fmaxf(mx.x, v.x); sm.x += v.x;
        mx.y = fmaxf(mx.y, v.y); sm.y += v.y;
        mx.z = fmaxf(mx.z, v.z); sm.z += v.z;
        mx.w = fmaxf(mx.w, v.w); sm.w += v.w;
    }
    float inv = 1.0f / (float)(end - start);
    float4* o = reinterpret_cast<float4*>(g_pooled + (long long)n * KDIM);
    o[lid] = mx;
    o[32 + lid] = make_float4(sm.x * inv, sm.y * inv, sm.z * inv, sm.w * inv);
}

// ---------------------------------------------------------------------------
// Kernel 3: out = relu(pooled @ W^T + b) via mma.sync tf32 (m16n8k8).
// CTA tile 128(M) x 128(N=full), K staged through smem in 8 chunks of 32.
// 8 warps as 4(M) x 2(N): warp tile 32x64 = 2 m-tiles x 8 n-tiles.
// Smem rows padded to 36 floats -> fragment loads are bank-conflict-free
// (bank = 4*g + l4, all 32 distinct).
// ---------------------------------------------------------------------------
#define BM 128
#define BK 32
#define A_STRIDE 36
#define G_THREADS 256

__device__ __forceinline__ void mma_tf32(float* d, const uint32_t* a, const uint32_t* b) {
    asm volatile(
        "mma.sync.aligned.m16n8k8.row.col.f32.tf32.tf32.f32 "
        "{%0,%1,%2,%3}, {%4,%5,%6,%7}, {%8,%9}, {%0,%1,%2,%3};"
        : "+f"(d[0]), "+f"(d[1]), "+f"(d[2]), "+f"(d[3])
        : "r"(a[0]), "r"(a[1]), "r"(a[2]), "r"(a[3]), "r"(b[0]), "r"(b[1]));
}

__global__ __launch_bounds__(G_THREADS) void gemm_kernel(const float* __restrict__ W,
                                                         const float* __restrict__ bias,
                                                         float* __restrict__ out) {
    __shared__ float As[BM][A_STRIDE];
    __shared__ float Bs[ODIM][A_STRIDE];
    __shared__ float sbias[ODIM];

    const int tid = threadIdx.x;
    const int wid = tid >> 5;
    const int lane = tid & 31;
    const int g  = lane >> 2;       // group id 0..7
    const int l4 = lane & 3;        // 0..3
    const int warpM = wid >> 1;     // 0..3  -> M offset warpM*32
    const int warpN = wid & 1;      // 0..1  -> N offset warpN*64
    const int bm = blockIdx.x * BM;

    if (tid < ODIM) sbias[tid] = bias[tid];

    float acc[2][8][4];
#pragma unroll
    for (int i = 0; i < 2; ++i)
#pragma unroll
        for (int j = 0; j < 8; ++j)
#pragma unroll
            for (int c = 0; c < 4; ++c) acc[i][j][c] = 0.f;

    for (int kt = 0; kt < KDIM; kt += BK) {
        // Stage A chunk: 128 rows x 32 floats (1024 float4, 4 per thread)
#pragma unroll
        for (int i = 0; i < 4; ++i) {
            int idx = tid + i * 256;
            int row = idx >> 3, c4 = idx & 7;
            float4 v = *(const float4*)&g_pooled[(long long)(bm + row) * KDIM + kt + c4 * 4];
            v.x = to_tf32(v.x); v.y = to_tf32(v.y); v.z = to_tf32(v.z); v.w = to_tf32(v.w);
            *(float4*)&As[row][c4 * 4] = v;
        }
        // Stage B chunk: W[128][kt:kt+32]
#pragma unroll
        for (int i = 0; i < 4; ++i) {
            int idx = tid + i * 256;
            int row = idx >> 3, c4 = idx & 7;
            float4 v = *(const float4*)&W[(long long)row * KDIM + kt + c4 * 4];
            v.x = to_tf32(v.x); v.y = to_tf32(v.y); v.z = to_tf32(v.z); v.w = to_tf32(v.w);
            *(float4*)&Bs[row][c4 * 4] = v;
        }
        __syncthreads();

#pragma unroll
        for (int k8 = 0; k8 < BK / 8; ++k8) {
            const int k0 = k8 * 8;
            uint32_t afrag[2][4];
#pragma unroll
            for (int i = 0; i < 2; ++i) {
                int mrow = warpM * 32 + i * 16 + g;
                afrag[i][0] = __float_as_uint(As[mrow][k0 + l4]);
                afrag[i][1] = __float_as_uint(As[mrow + 8][k0 + l4]);
                afrag[i][2] = __float_as_uint(As[mrow][k0 + l4 + 4]);
                afrag[i][3] = __float_as_uint(As[mrow + 8][k0 + l4 + 4]);
            }
            uint32_t bfrag[8][2];
#pragma unroll
            for (int j = 0; j < 8; ++j) {
                int nrow = warpN * 64 + j * 8 + g;
                bfrag[j][0] = __float_as_uint(Bs[nrow][k0 + l4]);
                bfrag[j][1] = __float_as_uint(Bs[nrow][k0 + l4 + 4]);
            }
#pragma unroll
            for (int i = 0; i < 2; ++i)
#pragma unroll
                for (int j = 0; j < 8; ++j)
                    mma_tf32(acc[i][j], afrag[i], bfrag[j]);
        }
        __syncthreads();
    }

    // Epilogue: bias + relu, direct float2 stores.
    // Tile (i,j): rows bm+warpM*32+i*16+{g, g+8}, cols warpN*64+j*8+2*l4+{0,1}
#pragma unroll
    for (int i = 0; i < 2; ++i) {
        int r0 = bm + warpM * 32 + i * 16 + g;
#pragma unroll
        for (int j = 0; j < 8; ++j) {
            int col = warpN * 64 + j * 8 + 2 * l4;
            float bx = sbias[col], by = sbias[col + 1];
            if (r0 < NSEG) {
                float2 o;
                o.x = fmaxf(acc[i][j][0] + bx, 0.f);
                o.y = fmaxf(acc[i][j][1] + by, 0.f);
                *(float2*)&out[(long long)r0 * ODIM + col] = o;
            }
            if (r0 + 8 < NSEG) {
                float2 o;
                o.x = fmaxf(acc[i][j][2] + bx, 0.f);
                o.y = fmaxf(acc[i][j][3] + by, 0.f);
                *(float2*)&out[(long long)(r0 + 8) * ODIM + col] = o;
            }
        }
    }
}

// ---------------------------------------------------------------------------
// Inputs (metadata order): obs_encoding (unused), lane_encoding, same_obs_mask,
// W, b. Output: float32 [NSEG, ODIM].
// ---------------------------------------------------------------------------
extern "C" void kernel_launch(void* const* d_in, const int* in_sizes, int n_in,
                              void* d_out, int out_size) {
    const float* lane = (const float*)d_in[1];
    const void*  seg  = d_in[2];
    const float* W    = (const float*)d_in[3];
    const float* bias = (const float*)d_in[4];
    float* out = (float*)d_out;

    boundary_kernel<<<(MROWS / 4 + 255) / 256, 256>>>(seg);
    pool_kernel<<<(NSEG + 3) / 4, 128>>>(lane);
    gemm_kernel<<<(NSEG_PAD + BM - 1) / BM, G_THREADS>>>(W, bias, out);
}

// round 5
// speedup vs baseline: 1.8294x; 1.1128x over previous
#include <cuda_runtime.h>
#include <math.h>
#include <stdint.h>

#define NSEG 50000
#define NSEG_PAD 50048
#define MROWS 800000
#define KDIM 256   // 2*D
#define ODIM 128

// Scratch (device globals zero-initialized -> padded rows of g_pooled are 0)
__device__ int   g_starts[NSEG + 1];
__device__ float g_pooled[(long long)NSEG_PAD * KDIM];

// Round-to-nearest tf32 (plain PTX, supported on compute_103 family target)
__device__ __forceinline__ float to_tf32(float x) {
    float r; asm("cvt.rna.tf32.f32 %0, %1;" : "=f"(r) : "f"(x)); return r;
}

// ---------------------------------------------------------------------------
// Kernel 1: segment boundary detection, 4 ids per thread (dtype probe for
// int64 vs int32: word [MROWS-1] is 0 iff ids are little-endian int64).
// ---------------------------------------------------------------------------
__global__ void boundary_kernel(const void* __restrict__ segraw) {
    int t = blockIdx.x * blockDim.x + threadIdx.x;
    int base = t * 4;
    if (base >= MROWS) return;
    const int* s32 = (const int*)segraw;
    bool is64 = (s32[MROWS - 1] == 0);
    int v[5];
    if (is64) {
        const long long* s = (const long long*)segraw;
        v[0] = (base > 0) ? (int)s[base - 1] : -1;
        longlong2 a = *(const longlong2*)&s[base];
        longlong2 b = *(const longlong2*)&s[base + 2];
        v[1] = (int)a.x; v[2] = (int)a.y; v[3] = (int)b.x; v[4] = (int)b.y;
    } else {
        v[0] = (base > 0) ? s32[base - 1] : -1;
        int4 a = *(const int4*)&s32[base];
        v[1] = a.x; v[2] = a.y; v[3] = a.z; v[4] = a.w;
    }
#pragma unroll
    for (int j = 0; j < 4; ++j)
        if (v[j + 1] != v[j]) g_starts[v[j + 1]] = base + j;
    if (base == 0) g_starts[NSEG] = MROWS;
}

// ---------------------------------------------------------------------------
// Kernel 2: segmented max+mean pooling. One warp per segment, lane owns a
// float4 of the 128-dim row (full 512B coalesced row per step).
// MLP fix: 4 back-to-back independent LDG.128 per lane per iteration, two
// accumulator chains. __ldcs on the stream (no reuse) keeps L2 free so
// g_pooled (51MB) stays resident for the GEMM's A reads.
// ---------------------------------------------------------------------------
__global__ void pool_kernel(const float* __restrict__ lane) {
    int warp = threadIdx.x >> 5;
    int lid  = threadIdx.x & 31;
    int n = blockIdx.x * 4 + warp;
    if (n >= NSEG) return;
    int start = g_starts[n];
    int len   = g_starts[n + 1] - start;

    const float4* p = reinterpret_cast<const float4*>(lane) + (long long)start * 32 + lid;

    float4 m0 = make_float4(-INFINITY, -INFINITY, -INFINITY, -INFINITY);
    float4 m1 = m0;
    float4 s0 = make_float4(0.f, 0.f, 0.f, 0.f);
    float4 s1 = s0;

    int r = 0;
    for (; r + 4 <= len; r += 4) {
        float4 v0 = __ldcs(p);
        float4 v1 = __ldcs(p + 32);
        float4 v2 = __ldcs(p + 64);
        float4 v3 = __ldcs(p + 96);
        p += 128;
        m0.x = fmaxf(m0.x, v0.x); s0.x += v0.x;
        m0.y = fmaxf(m0.y, v0.y); s0.y += v0.y;
        m0.z = fmaxf(m0.z, v0.z); s0.z += v0.z;
        m0.w = fmaxf(m0.w, v0.w); s0.w += v0.w;
        m1.x = fmaxf(m1.x, v1.x); s1.x += v1.x;
        m1.y = fmaxf(m1.y, v1.y); s1.y += v1.y;
        m1.z = fmaxf(m1.z, v1.z); s1.z += v1.z;
        m1.w = fmaxf(m1.w, v1.w); s1.w += v1.w;
        m0.x = fmaxf(m0.x, v2.x); s0.x += v2.x;
        m0.y = fmaxf(m0.y, v2.y); s0.y += v2.y;
        m0.z = fmaxf(m0.z, v2.z); s0.z += v2.z;
        m0.w = fmaxf(m0.w, v2.w); s0.w += v2.w;
        m1.x = fmaxf(m1.x, v3.x); s1.x += v3.x;
        m1.y = fmaxf(m1.y, v3.y); s1.y += v3.y;
        m1.z = fmaxf(m1.z, v3.z); s1.z += v3.z;
        m1.w = fmaxf(m1.w, v3.w); s1.w += v3.w;
    }
    for (; r < len; ++r) {
        float4 v = __ldcs(p);
        p += 32;
        m0.x = fmaxf(m0.x, v.x); s0.x += v.x;
        m0.y = fmaxf(m0.y, v.y); s0.y += v.y;
        m0.z = fmaxf(m0.z, v.z); s0.z += v.z;
        m0.w = fmaxf(m0.w, v.w); s0.w += v.w;
    }

    float4 mx, sm;
    mx.x = fmaxf(m0.x, m1.x); sm.x = s0.x + s1.x;
    mx.y = fmaxf(m0.y, m1.y); sm.y = s0.y + s1.y;
    mx.z = fmaxf(m0.z, m1.z); sm.z = s0.z + s1.z;
    mx.w = fmaxf(m0.w, m1.w); sm.w = s0.w + s1.w;

    float inv = 1.0f / (float)len;
    float4* o = reinterpret_cast<float4*>(g_pooled + (long long)n * KDIM);
    o[lid] = mx;
    o[32 + lid] = make_float4(sm.x * inv, sm.y * inv, sm.z * inv, sm.w * inv);
}

// ---------------------------------------------------------------------------
// Kernel 3: out = relu(pooled @ W^T + b) via mma.sync tf32 (m16n8k8).
// Identical to R4 (known-good, ~17us).
// ---------------------------------------------------------------------------
#define BM 128
#define BK 32
#define A_STRIDE 36
#define G_THREADS 256

__device__ __forceinline__ void mma_tf32(float* d, const uint32_t* a, const uint32_t* b) {
    asm volatile(
        "mma.sync.aligned.m16n8k8.row.col.f32.tf32.tf32.f32 "
        "{%0,%1,%2,%3}, {%4,%5,%6,%7}, {%8,%9}, {%0,%1,%2,%3};"
        : "+f"(d[0]), "+f"(d[1]), "+f"(d[2]), "+f"(d[3])
        : "r"(a[0]), "r"(a[1]), "r"(a[2]), "r"(a[3]), "r"(b[0]), "r"(b[1]));
}

__global__ __launch_bounds__(G_THREADS) void gemm_kernel(const float* __restrict__ W,
                                                         const float* __restrict__ bias,
                                                         float* __restrict__ out) {
    __shared__ float As[BM][A_STRIDE];
    __shared__ float Bs[ODIM][A_STRIDE];
    __shared__ float sbias[ODIM];

    const int tid = threadIdx.x;
    const int wid = tid >> 5;
    const int lane = tid & 31;
    const int g  = lane >> 2;       // group id 0..7
    const int l4 = lane & 3;        // 0..3
    const int warpM = wid >> 1;     // 0..3  -> M offset warpM*32
    const int warpN = wid & 1;      // 0..1  -> N offset warpN*64
    const int bm = blockIdx.x * BM;

    if (tid < ODIM) sbias[tid] = bias[tid];

    float acc[2][8][4];
#pragma unroll
    for (int i = 0; i < 2; ++i)
#pragma unroll
        for (int j = 0; j < 8; ++j)
#pragma unroll
            for (int c = 0; c < 4; ++c) acc[i][j][c] = 0.f;

    for (int kt = 0; kt < KDIM; kt += BK) {
        // Stage A chunk: 128 rows x 32 floats (1024 float4, 4 per thread)
#pragma unroll
        for (int i = 0; i < 4; ++i) {
            int idx = tid + i * 256;
            int row = idx >> 3, c4 = idx & 7;
            float4 v = *(const float4*)&g_pooled[(long long)(bm + row) * KDIM + kt + c4 * 4];
            v.x = to_tf32(v.x); v.y = to_tf32(v.y); v.z = to_tf32(v.z); v.w = to_tf32(v.w);
            *(float4*)&As[row][c4 * 4] = v;
        }
        // Stage B chunk: W[128][kt:kt+32]
#pragma unroll
        for (int i = 0; i < 4; ++i) {
            int idx = tid + i * 256;
            int row = idx >> 3, c4 = idx & 7;
            float4 v = *(const float4*)&W[(long long)row * KDIM + kt + c4 * 4];
            v.x = to_tf32(v.x); v.y = to_tf32(v.y); v.z = to_tf32(v.z); v.w = to_tf32(v.w);
            *(float4*)&Bs[row][c4 * 4] = v;
        }
        __syncthreads();

#pragma unroll
        for (int k8 = 0; k8 < BK / 8; ++k8) {
            const int k0 = k8 * 8;
            uint32_t afrag[2][4];
#pragma unroll
            for (int i = 0; i < 2; ++i) {
                int mrow = warpM * 32 + i * 16 + g;
                afrag[i][0] = __float_as_uint(As[mrow][k0 + l4]);
                afrag[i][1] = __float_as_uint(As[mrow + 8][k0 + l4]);
                afrag[i][2] = __float_as_uint(As[mrow][k0 + l4 + 4]);
                afrag[i][3] = __float_as_uint(As[mrow + 8][k0 + l4 + 4]);
            }
            uint32_t bfrag[8][2];
#pragma unroll
            for (int j = 0; j < 8; ++j) {
                int nrow = warpN * 64 + j * 8 + g;
                bfrag[j][0] = __float_as_uint(Bs[nrow][k0 + l4]);
                bfrag[j][1] = __float_as_uint(Bs[nrow][k0 + l4 + 4]);
            }
#pragma unroll
            for (int i = 0; i < 2; ++i)
#pragma unroll
                for (int j = 0; j < 8; ++j)
                    mma_tf32(acc[i][j], afrag[i], bfrag[j]);
        }
        __syncthreads();
    }

    // Epilogue: bias + relu, direct float2 stores.
#pragma unroll
    for (int i = 0; i < 2; ++i) {
        int r0 = bm + warpM * 32 + i * 16 + g;
#pragma unroll
        for (int j = 0; j < 8; ++j) {
            int col = warpN * 64 + j * 8 + 2 * l4;
            float bx = sbias[col], by = sbias[col + 1];
            if (r0 < NSEG) {
                float2 o;
                o.x = fmaxf(acc[i][j][0] + bx, 0.f);
                o.y = fmaxf(acc[i][j][1] + by, 0.f);
                *(float2*)&out[(long long)r0 * ODIM + col] = o;
            }
            if (r0 + 8 < NSEG) {
                float2 o;
                o.x = fmaxf(acc[i][j][2] + bx, 0.f);
                o.y = fmaxf(acc[i][j][3] + by, 0.f);
                *(float2*)&out[(long long)(r0 + 8) * ODIM + col] = o;
            }
        }
    }
}

// ---------------------------------------------------------------------------
// Inputs (metadata order): obs_encoding (unused), lane_encoding, same_obs_mask,
// W, b. Output: float32 [NSEG, ODIM].
// ---------------------------------------------------------------------------
extern "C" void kernel_launch(void* const* d_in, const int* in_sizes, int n_in,
                              void* d_out, int out_size) {
    const float* lane = (const float*)d_in[1];
    const void*  seg  = d_in[2];
    const float* W    = (const float*)d_in[3];
    const float* bias = (const float*)d_in[4];
    float* out = (float*)d_out;

    boundary_kernel<<<(MROWS / 4 + 255) / 256, 256>>>(seg);
    pool_kernel<<<(NSEG + 3) / 4, 128>>>(lane);
    gemm_kernel<<<(NSEG_PAD + BM - 1) / BM, G_THREADS>>>(W, bias, out);
}